// round 15
// baseline (speedup 1.0000x reference)
#include <cuda_runtime.h>
#include <cuda_bf16.h>
#include <cuda_fp16.h>

// ---------------------------------------------------------------------------
// Problem constants
// ---------------------------------------------------------------------------
#define D_MODEL  1024
#define D_INNER  2048
#define D_STATE  16
#define D_CONV   4
#define DT_RANK  64
#define BATCH    2
#define SEQLEN   2048
#define MROWS    (BATCH * SEQLEN)         // 4096
#define XDBL_N   (DT_RANK + 2 * D_STATE)  // 96
#define KSLICES  8                        // split-K factor for GEMM2

// ---------------------------------------------------------------------------
// Scratch (static device globals; no allocation allowed)
// ---------------------------------------------------------------------------
__device__ float  g_xraw [MROWS * D_INNER];    // x pre-conv (fp32)
__device__ __half g_zs_h [MROWS * D_INNER];    // silu(z) fp16 (scan input)
__device__ float  g_bc   [MROWS * 32];         // B|C fp32 (scan)
__device__ float  g_delta[MROWS * D_INNER];    // softplus(dt) fp32
__device__ float  g_xdbl_part[KSLICES * MROWS * XDBL_N];  // split-K partials

// fp16 single activations (A of GEMM1/4)
__device__ __half g_hid_h[MROWS * D_MODEL];
__device__ __half g_u_h  [MROWS * D_INNER];
// bf16 hi/lo activations (A of GEMM2/3 + scan xc source)
__device__ __nv_bfloat16 g_xc_h [MROWS * D_INNER];
__device__ __nv_bfloat16 g_xc_l [MROWS * D_INNER];
__device__ __nv_bfloat16 g_dt_h [MROWS * DT_RANK];
__device__ __nv_bfloat16 g_dt_l [MROWS * DT_RANK];

__device__ float g_Aneg [D_INNER * D_STATE];   // -exp(A_log) * log2(e)

// transposed ([N][K]) weights: fp16 SINGLE for GEMM1/4, bf16 hi/lo for GEMM2/3
__device__ __half        g_WinT_h [4096 * 1024];
__device__ __half        g_WoutT_h[1024 * 2048];
__device__ __nv_bfloat16 g_WxT_h  [96 * 2048];
__device__ __nv_bfloat16 g_WxT_l  [96 * 2048];
__device__ __nv_bfloat16 g_WdtT_h [2048 * 64];
__device__ __nv_bfloat16 g_WdtT_l [2048 * 64];

__device__ __forceinline__ float sigmoidf_(float v) {
    return 1.0f / (1.0f + __expf(-v));
}
__device__ __forceinline__ unsigned smem_u32(const void* p) {
    unsigned a;
    asm("{ .reg .u64 t; cvta.to.shared.u64 t, %1; cvt.u32.u64 %0, t; }"
        : "=r"(a) : "l"(p));
    return a;
}
__device__ __forceinline__ unsigned pkbf(float a, float b) {
    __nv_bfloat162 p = __floats2bfloat162_rn(a, b);
    return *reinterpret_cast<unsigned*>(&p);
}
__device__ __forceinline__ unsigned pkhf(float a, float b) {
    __half2 p = __floats2half2_rn(a, b);
    return *reinterpret_cast<unsigned*>(&p);
}
__device__ __forceinline__ float residb(float v) {
    return v - __bfloat162float(__float2bfloat16(v));
}

#define LDSM4(r, addr)                                                        \
    asm volatile("ldmatrix.sync.aligned.m8n8.x4.shared.b16 {%0,%1,%2,%3}, [%4];" \
        : "=r"((r)[0]), "=r"((r)[1]), "=r"((r)[2]), "=r"((r)[3]) : "r"(addr))

#define MMABF16(c, a, b0, b1)                                                 \
    asm volatile("mma.sync.aligned.m16n8k16.row.col.f32.bf16.bf16.f32 "       \
        "{%0,%1,%2,%3}, {%4,%5,%6,%7}, {%8,%9}, {%0,%1,%2,%3};"               \
        : "+f"((c)[0]), "+f"((c)[1]), "+f"((c)[2]), "+f"((c)[3])              \
        : "r"((a)[0]), "r"((a)[1]), "r"((a)[2]), "r"((a)[3]), "r"(b0), "r"(b1))

#define MMAF16(c, a, b0, b1)                                                  \
    asm volatile("mma.sync.aligned.m16n8k16.row.col.f32.f16.f16.f32 "         \
        "{%0,%1,%2,%3}, {%4,%5,%6,%7}, {%8,%9}, {%0,%1,%2,%3};"               \
        : "+f"((c)[0]), "+f"((c)[1]), "+f"((c)[2]), "+f"((c)[3])              \
        : "r"((a)[0]), "r"((a)[1]), "r"((a)[2]), "r"((a)[3]), "r"(b0), "r"(b1))

__device__ __forceinline__ void cpa16(unsigned dst, const void* src, int sz) {
    asm volatile("cp.async.cg.shared.global [%0], [%1], 16, %2;"
                 :: "r"(dst), "l"(src), "r"(sz));
}
#define CPA_COMMIT() asm volatile("cp.async.commit_group;" ::: "memory")
#define CPA_WAIT0()  asm volatile("cp.async.wait_group 0;" ::: "memory")
#define CPA_WAIT1()  asm volatile("cp.async.wait_group 1;" ::: "memory")

// ---------------------------------------------------------------------------
// Weight prep
// ---------------------------------------------------------------------------
__global__ void prep_w_bf(const float* __restrict__ W,
                          __nv_bfloat16* __restrict__ hT,
                          __nv_bfloat16* __restrict__ lT, int K, int N)
{
    __shared__ float t[32][33];
    int k0 = blockIdx.x * 32, n0 = blockIdx.y * 32;
    int tx = threadIdx.x, ty = threadIdx.y;
#pragma unroll
    for (int i = 0; i < 4; i++) {
        int k = k0 + ty + i * 8;
        t[ty + i * 8][tx] = (k < K && n0 + tx < N) ? W[(size_t)k * N + n0 + tx] : 0.f;
    }
    __syncthreads();
#pragma unroll
    for (int i = 0; i < 4; i++) {
        int n = n0 + ty + i * 8, k = k0 + tx;
        if (n < N && k < K) {
            float v = t[tx][ty + i * 8];
            __nv_bfloat16 h = __float2bfloat16(v);
            hT[(size_t)n * K + k] = h;
            lT[(size_t)n * K + k] = __float2bfloat16(v - __bfloat162float(h));
        }
    }
}

// fp32 -> transposed single fp16 [N][K]
__global__ void prep_w_f16s(const float* __restrict__ W,
                            __half* __restrict__ hT, int K, int N)
{
    __shared__ float t[32][33];
    int k0 = blockIdx.x * 32, n0 = blockIdx.y * 32;
    int tx = threadIdx.x, ty = threadIdx.y;
#pragma unroll
    for (int i = 0; i < 4; i++) {
        int k = k0 + ty + i * 8;
        t[ty + i * 8][tx] = (k < K && n0 + tx < N) ? W[(size_t)k * N + n0 + tx] : 0.f;
    }
    __syncthreads();
#pragma unroll
    for (int i = 0; i < 4; i++) {
        int n = n0 + ty + i * 8, k = k0 + tx;
        if (n < N && k < K)
            hT[(size_t)n * K + k] = __float2half_rn(t[tx][ty + i * 8]);
    }
}

// hidden fp32 -> fp16 single
__global__ void conv_hidden(const float* __restrict__ H)
{
    size_t i = (size_t)(blockIdx.x * blockDim.x + threadIdx.x) * 8;
    if (i >= (size_t)MROWS * D_MODEL) return;
    float4 v0 = *(const float4*)(H + i);
    float4 v1 = *(const float4*)(H + i + 4);
    uint4 h = make_uint4(pkhf(v0.x, v0.y), pkhf(v0.z, v0.w),
                         pkhf(v1.x, v1.y), pkhf(v1.z, v1.w));
    *(uint4*)(g_hid_h + i) = h;
}

// ---------------------------------------------------------------------------
// warp-MMA GEMM, cp.async pipelined.
// MODE 0: bf16 3-term (A hi/lo + B hi/lo), 2-stage      (GEMM2/3)
// MODE 2: fp16 single A x single B, 1 MMA/k16, 3-stage  (GEMM1/4)
// EPI 0: plain  EPI 1: xz split (x fp32, silu(z) fp16)  EPI 2: bias+softplus
// EPI 4: split-K partial
// ---------------------------------------------------------------------------
#define APITCH 80         // bytes per smem row (40 halves)
#define TILEB  10240      // one 128-row tile

template <int EPI, int MODE>
__global__ __launch_bounds__(256, 2)
void mma_gemm(const void* __restrict__ Ah_, const void* __restrict__ Al_,
              const void* __restrict__ BTh_, const void* __restrict__ BTl_,
              float* __restrict__ C0, float* __restrict__ C1,
              const float* __restrict__ bias,
              int M, int N, int K, int lda, int ldc)
{
    constexpr int ATILES = (MODE == 0) ? 2 : 1;
    constexpr int BTILES = (MODE == 2) ? 1 : 2;
    constexpr int NSTAGE = (MODE == 0) ? 2 : 3;
    constexpr int SB = (ATILES + BTILES) * TILEB;   // stage bytes

    extern __shared__ __align__(16) char sm[];
    const unsigned short* Ah = (const unsigned short*)Ah_;
    const unsigned short* Al = (const unsigned short*)Al_;
    const unsigned short* BTh = (const unsigned short*)BTh_;
    const unsigned short* BTl = (const unsigned short*)BTl_;

    const int tid = threadIdx.x, lane = tid & 31, wid = tid >> 5;
    const int row0 = blockIdx.y * 128, col0 = blockIdx.x * 128;
    const int wm = (wid >> 2) * 64, wn = (wid & 3) * 32;

    const int lrow = tid >> 1;
    const int kb = (tid & 1) * 16;

    float acc[4][4][4];
#pragma unroll
    for (int i = 0; i < 4; i++)
#pragma unroll
        for (int j = 0; j < 4; j++)
#pragma unroll
            for (int q = 0; q < 4; q++) acc[i][j][q] = 0.f;

    const unsigned smb = smem_u32(sm);
    const unsigned aOff = (wm + (lane & 15)) * APITCH + (lane >> 4) * 16;
    const unsigned bOff = ATILES * TILEB + (wn + (lane & 15)) * APITCH + (lane >> 4) * 16;

    const int gnB = col0 + lrow;
    const int bsz = (gnB < N) ? 16 : 0;
    const int gnC = (gnB < N) ? gnB : (N - 1);
    const unsigned dA = lrow * APITCH + kb * 2;
    const unsigned dB = ATILES * TILEB + lrow * APITCH + kb * 2;

    const int ktn = (K >> 5) / gridDim.z;
    const int ktb = blockIdx.z * ktn;

    auto issue = [&](int kt, int st) {
        const int k0 = kt << 5;
        const unsigned sbase = smb + st * SB;
        const unsigned short* aph = Ah + (size_t)(row0 + lrow) * lda + k0 + kb;
        cpa16(sbase + dA, aph, 16);
        cpa16(sbase + dA + 16, aph + 8, 16);
        if (MODE == 0) {
            const unsigned short* apl = Al + (size_t)(row0 + lrow) * lda + k0 + kb;
            cpa16(sbase + dA + TILEB, apl, 16);
            cpa16(sbase + dA + TILEB + 16, apl + 8, 16);
        }
        const unsigned short* bph = BTh + (size_t)gnC * K + k0 + kb;
        cpa16(sbase + dB, bph, bsz);
        cpa16(sbase + dB + 16, bph + 8, bsz);
        if (MODE != 2) {
            const unsigned short* bpl = BTl + (size_t)gnC * K + k0 + kb;
            cpa16(sbase + dB + TILEB, bpl, bsz);
            cpa16(sbase + dB + TILEB + 16, bpl + 8, bsz);
        }
        CPA_COMMIT();
    };

    auto compute = [&](int st) {
        const unsigned sbase = smb + st * SB;
        const unsigned aHi = sbase + aOff;
        const unsigned bHi = sbase + bOff;
#pragma unroll
        for (int ks = 0; ks < 2; ks++) {
            const unsigned koff = ks * 32;
            unsigned ah[4][4], bh[2][4];
#pragma unroll
            for (int mt = 0; mt < 4; mt++)
                LDSM4(ah[mt], aHi + mt * (16 * APITCH) + koff);
#pragma unroll
            for (int g = 0; g < 2; g++)
                LDSM4(bh[g], bHi + g * (16 * APITCH) + koff);
            if (MODE == 0) {
                unsigned al[4][4], bl[2][4];
#pragma unroll
                for (int mt = 0; mt < 4; mt++)
                    LDSM4(al[mt], aHi + TILEB + mt * (16 * APITCH) + koff);
#pragma unroll
                for (int g = 0; g < 2; g++)
                    LDSM4(bl[g], bHi + TILEB + g * (16 * APITCH) + koff);
#pragma unroll
                for (int mt = 0; mt < 4; mt++)
#pragma unroll
                    for (int nt = 0; nt < 4; nt++) {
                        const int g = nt >> 1, o = nt & 1;
                        MMABF16(acc[mt][nt], ah[mt], bh[g][o], bh[g][2 + o]);
                        MMABF16(acc[mt][nt], ah[mt], bl[g][o], bl[g][2 + o]);
                        MMABF16(acc[mt][nt], al[mt], bh[g][o], bh[g][2 + o]);
                    }
            } else {
#pragma unroll
                for (int mt = 0; mt < 4; mt++)
#pragma unroll
                    for (int nt = 0; nt < 4; nt++) {
                        const int g = nt >> 1, o = nt & 1;
                        MMAF16(acc[mt][nt], ah[mt], bh[g][o], bh[g][2 + o]);
                    }
            }
        }
    };

    if (NSTAGE == 3) {
        // 3-stage, one barrier per iteration (stage (t+2)%3 was consumed at t-1)
        issue(ktb, 0);
        if (ktn > 1) issue(ktb + 1, 1);
        for (int t = 0; t < ktn; t++) {
            if (t + 1 < ktn) CPA_WAIT1(); else CPA_WAIT0();
            __syncthreads();
            if (t + 2 < ktn) issue(ktb + t + 2, (t + 2) % 3);
            compute(t % 3);
        }
    } else {
        issue(ktb, 0);
        for (int t = 0; t < ktn; t++) {
            const int cur = t & 1;
            if (t + 1 < ktn) issue(ktb + t + 1, cur ^ 1);
            if (t + 1 < ktn) CPA_WAIT1(); else CPA_WAIT0();
            __syncthreads();
            compute(cur);
            __syncthreads();
        }
    }

    // ---- epilogue ----
    const int g = lane >> 2, tg = (lane & 3) * 2;
#pragma unroll
    for (int mt = 0; mt < 4; mt++) {
#pragma unroll
        for (int nt = 0; nt < 4; nt++) {
            float* c = acc[mt][nt];
            int r0 = row0 + wm + mt * 16 + g;
            int r1 = r0 + 8;
            int cc = col0 + wn + nt * 8 + tg;
            if (EPI == 0) {
                if (cc < N) {
                    *(float2*)&C0[(size_t)r0 * ldc + cc] = make_float2(c[0], c[1]);
                    *(float2*)&C0[(size_t)r1 * ldc + cc] = make_float2(c[2], c[3]);
                }
            } else if (EPI == 1) {
                int h = cc >> 1;    // cc even: c0/c2 -> x col h, c1/c3 -> z col h
                __half* Z = (__half*)C1;
                C0[(size_t)r0 * D_INNER + h] = c[0];
                Z [(size_t)r0 * D_INNER + h] = __float2half_rn(c[1] * sigmoidf_(c[1]));
                C0[(size_t)r1 * D_INNER + h] = c[2];
                Z [(size_t)r1 * D_INNER + h] = __float2half_rn(c[3] * sigmoidf_(c[3]));
            } else if (EPI == 2) {
                float b0v = bias[cc], b1v = bias[cc + 1];
                float a0 = c[0] + b0v, a1 = c[1] + b1v;
                float a2 = c[2] + b0v, a3 = c[3] + b1v;
                a0 = (a0 > 20.f) ? a0 : log1pf(__expf(a0));
                a1 = (a1 > 20.f) ? a1 : log1pf(__expf(a1));
                a2 = (a2 > 20.f) ? a2 : log1pf(__expf(a2));
                a3 = (a3 > 20.f) ? a3 : log1pf(__expf(a3));
                *(float2*)&C0[(size_t)r0 * ldc + cc] = make_float2(a0, a1);
                *(float2*)&C0[(size_t)r1 * ldc + cc] = make_float2(a2, a3);
            } else { // EPI 4: split-K partial store
                if (cc < N) {
                    float* dst = C0 + (size_t)blockIdx.z * M * ldc;
                    *(float2*)&dst[(size_t)r0 * ldc + cc] = make_float2(c[0], c[1]);
                    *(float2*)&dst[(size_t)r1 * ldc + cc] = make_float2(c[2], c[3]);
                }
            }
        }
    }
}

// ---------------------------------------------------------------------------
// finalize split-K xdbl
// ---------------------------------------------------------------------------
__global__ void finalize_xdbl()
{
    int idx = blockIdx.x * blockDim.x + threadIdx.x;
    if (idx >= MROWS * (XDBL_N / 4)) return;
    int row = idx / 24;
    int c4 = (idx % 24) * 4;
    float4 s = make_float4(0.f, 0.f, 0.f, 0.f);
#pragma unroll
    for (int z = 0; z < KSLICES; z++) {
        float4 v = *(const float4*)&g_xdbl_part[(size_t)z * MROWS * XDBL_N
                                                + (size_t)row * XDBL_N + c4];
        s.x += v.x; s.y += v.y; s.z += v.z; s.w += v.w;
    }
    if (c4 < DT_RANK) {
        size_t o = (size_t)row * DT_RANK + c4;
        *(uint2*)&g_dt_h[o] = make_uint2(pkbf(s.x, s.y), pkbf(s.z, s.w));
        *(uint2*)&g_dt_l[o] = make_uint2(pkbf(residb(s.x), residb(s.y)),
                                         pkbf(residb(s.z), residb(s.w)));
    } else {
        *(float4*)&g_bc[(size_t)row * 32 + (c4 - DT_RANK)] = s;
    }
}

// ---------------------------------------------------------------------------
// Depthwise conv (SAME pad lo=1 hi=2) + bias + silu; writes bf16 hi/lo ONLY
// (scan reconstructs fp32 as hi+lo; fp32 buffer eliminated)
// ---------------------------------------------------------------------------
__global__ void conv_silu_kernel(const float* __restrict__ ck,
                                 const float* __restrict__ cb)
{
    int idx = blockIdx.x * blockDim.x + threadIdx.x;
    if (idx >= MROWS * (D_INNER / 4)) return;
    int row = idx >> 9;
    int d = (idx & 511) << 2;
    int b = row >> 11;
    int l = row & (SEQLEN - 1);

    float4 acc = *(const float4*)&cb[d];
#pragma unroll
    for (int w = 0; w < D_CONV; w++) {
        int ls = l + w - 1;
        if (ls >= 0 && ls < SEQLEN) {
            float4 xv = *(const float4*)&g_xraw[((size_t)(b * SEQLEN + ls)) * D_INNER + d];
            float4 kv = *(const float4*)&ck[w * D_INNER + d];
            acc.x += xv.x * kv.x; acc.y += xv.y * kv.y;
            acc.z += xv.z * kv.z; acc.w += xv.w * kv.w;
        }
    }
    acc.x *= sigmoidf_(acc.x); acc.y *= sigmoidf_(acc.y);
    acc.z *= sigmoidf_(acc.z); acc.w *= sigmoidf_(acc.w);
    size_t o = (size_t)row * D_INNER + d;
    *(uint2*)&g_xc_h[o] = make_uint2(pkbf(acc.x, acc.y), pkbf(acc.z, acc.w));
    *(uint2*)&g_xc_l[o] = make_uint2(pkbf(residb(acc.x), residb(acc.y)),
                                     pkbf(residb(acc.z), residb(acc.w)));
}

// A = -exp(A_log) * log2(e)  (scan uses exp2f)
__global__ void aneg_kernel(const float* __restrict__ A_log)
{
    int i = blockIdx.x * blockDim.x + threadIdx.x;
    if (i < D_INNER * D_STATE) g_Aneg[i] = -__expf(A_log[i]) * 1.4426950408889634f;
}

// ---------------------------------------------------------------------------
// Selective scan fused with gating; xc = bf16 hi+lo, zs = fp16, u -> fp16
// ---------------------------------------------------------------------------
#define TCHUNK 64

__global__ __launch_bounds__(256)
void scan_kernel(const float* __restrict__ Dvec)
{
    __shared__ float sB [TCHUNK][D_STATE];
    __shared__ float sC [TCHUNK][D_STATE];
    __shared__ float sDl[TCHUNK][16];
    __shared__ float sX [TCHUNK][16];
    __shared__ float sZ [TCHUNK][16];

    const int tid = threadIdx.x;
    const int b = blockIdx.x >> 7;
    const int d0 = (blockIdx.x & 127) * 16;
    const int warp = tid >> 5;
    const int half = (tid >> 4) & 1;
    const int n = tid & 15;
    const int dl = warp * 2 + half;
    const int d = d0 + dl;

    const float An = g_Aneg[d * D_STATE + n];   // includes log2(e)
    const float Dd = Dvec[d];
    float st = 0.0f;
    const long base_row = (long)b * SEQLEN;

    for (int c = 0; c < SEQLEN / TCHUNK; c++) {
        const int t0 = c * TCHUNK;
        __syncthreads();
#pragma unroll
        for (int r = 0; r < 4; r++) {
            int i = tid + r * 256;
            int tt = i >> 4, nn = i & 15;
            long row = base_row + t0 + tt;
            sB [tt][nn] = g_bc[row * 32 + nn];
            sC [tt][nn] = g_bc[row * 32 + 16 + nn];
            sDl[tt][nn] = g_delta[row * D_INNER + d0 + nn];
            sX [tt][nn] = __bfloat162float(g_xc_h[row * D_INNER + d0 + nn])
                        + __bfloat162float(g_xc_l[row * D_INNER + d0 + nn]);
            sZ [tt][nn] = __half2float(g_zs_h[row * D_INNER + d0 + nn]);
        }
        __syncthreads();

#pragma unroll 4
        for (int tt = 0; tt < TCHUNK; tt++) {
            float dv = sDl[tt][dl];
            float xv = sX[tt][dl];
            float bv = sB[tt][n];
            float cv = sC[tt][n];
            float dA = exp2f(dv * An);
            st = __fmaf_rn(dA, st, dv * xv * bv);
            float p = st * cv;
            p += __shfl_xor_sync(0xffffffffu, p, 1, 16);
            p += __shfl_xor_sync(0xffffffffu, p, 2, 16);
            p += __shfl_xor_sync(0xffffffffu, p, 4, 16);
            p += __shfl_xor_sync(0xffffffffu, p, 8, 16);
            if (n == 0) {
                long row = base_row + t0 + tt;
                float uv = (p + xv * Dd) * sZ[tt][dl];
                g_u_h[row * D_INNER + d] = __float2half_rn(uv);
            }
        }
    }
}

// ---------------------------------------------------------------------------
// Host launcher
// ---------------------------------------------------------------------------
extern "C" void kernel_launch(void* const* d_in, const int* in_sizes, int n_in,
                              void* d_out, int out_size)
{
    const float* hidden = (const float*)d_in[0];
    const float* W_in   = (const float*)d_in[1];
    const float* ck     = (const float*)d_in[2];
    const float* cb     = (const float*)d_in[3];
    const float* W_x    = (const float*)d_in[4];
    const float* W_dt   = (const float*)d_in[5];
    const float* b_dt   = (const float*)d_in[6];
    const float* A_log  = (const float*)d_in[7];
    const float* Dvec   = (const float*)d_in[8];
    const float* W_out  = (const float*)d_in[9];
    float* out = (float*)d_out;

    void *p_xraw, *p_zsh, *p_delta, *p_part;
    cudaGetSymbolAddress(&p_xraw,  g_xraw);
    cudaGetSymbolAddress(&p_zsh,   g_zs_h);
    cudaGetSymbolAddress(&p_delta, g_delta);
    cudaGetSymbolAddress(&p_part,  g_xdbl_part);

    void *p_hidh, *p_xch, *p_xcl, *p_dth, *p_dtl, *p_uh;
    cudaGetSymbolAddress(&p_hidh, g_hid_h);
    cudaGetSymbolAddress(&p_xch,  g_xc_h);   cudaGetSymbolAddress(&p_xcl,  g_xc_l);
    cudaGetSymbolAddress(&p_dth,  g_dt_h);   cudaGetSymbolAddress(&p_dtl,  g_dt_l);
    cudaGetSymbolAddress(&p_uh,   g_u_h);

    void *p_winh, *p_wxh, *p_wxl, *p_wdth, *p_wdtl, *p_wouth;
    cudaGetSymbolAddress(&p_winh,  g_WinT_h);
    cudaGetSymbolAddress(&p_wxh,   g_WxT_h);   cudaGetSymbolAddress(&p_wxl,   g_WxT_l);
    cudaGetSymbolAddress(&p_wdth,  g_WdtT_h);  cudaGetSymbolAddress(&p_wdtl,  g_WdtT_l);
    cudaGetSymbolAddress(&p_wouth, g_WoutT_h);

    const int SM_M0 = 2 * 4 * TILEB;   // MODE0 2-stage: 81920
    const int SM_M2 = 3 * 2 * TILEB;   // MODE2 3-stage: 61440
    cudaFuncSetAttribute(mma_gemm<1,2>, cudaFuncAttributeMaxDynamicSharedMemorySize, SM_M2);
    cudaFuncSetAttribute(mma_gemm<0,2>, cudaFuncAttributeMaxDynamicSharedMemorySize, SM_M2);
    cudaFuncSetAttribute(mma_gemm<4,0>, cudaFuncAttributeMaxDynamicSharedMemorySize, SM_M0);
    cudaFuncSetAttribute(mma_gemm<2,0>, cudaFuncAttributeMaxDynamicSharedMemorySize, SM_M0);

    dim3 tb(32, 8);
    // 0) input conversion + weight prep
    conv_hidden<<<(MROWS * D_MODEL / 8 + 255) / 256, 256>>>(hidden);
    prep_w_f16s<<<dim3(D_MODEL / 32, (2 * D_INNER) / 32), tb>>>(W_in,
        (__half*)p_winh, D_MODEL, 2 * D_INNER);
    prep_w_bf<<<dim3(D_INNER / 32, 3), tb>>>(W_x,
        (__nv_bfloat16*)p_wxh, (__nv_bfloat16*)p_wxl, D_INNER, XDBL_N);
    prep_w_bf<<<dim3(DT_RANK / 32, D_INNER / 32), tb>>>(W_dt,
        (__nv_bfloat16*)p_wdth, (__nv_bfloat16*)p_wdtl, DT_RANK, D_INNER);
    prep_w_f16s<<<dim3(D_INNER / 32, D_MODEL / 32), tb>>>(W_out,
        (__half*)p_wouth, D_INNER, D_MODEL);

    // 1) xz = hidden @ W_in (fp16 single) ; split into x_raw fp32 / silu(z) fp16
    {
        dim3 grid((2 * D_INNER) / 128, MROWS / 128, 1);
        mma_gemm<1,2><<<grid, 256, SM_M2>>>(
            p_hidh, nullptr, p_winh, nullptr,
            (float*)p_xraw, (float*)p_zsh, nullptr,
            MROWS, 2 * D_INNER, D_MODEL, D_MODEL, 2 * D_INNER);
    }
    aneg_kernel<<<(D_INNER * D_STATE + 255) / 256, 256>>>(A_log);
    // 2) depthwise conv + bias + silu (bf16 hi/lo only)
    {
        int threads = MROWS * (D_INNER / 4);
        conv_silu_kernel<<<(threads + 255) / 256, 256>>>(ck, cb);
    }
    // 3) x_dbl = xc @ W_x (bf16 3-term, split-K x8 -> partials)
    {
        dim3 grid(1, MROWS / 128, KSLICES);
        mma_gemm<4,0><<<grid, 256, SM_M0>>>(
            p_xch, p_xcl, p_wxh, p_wxl,
            (float*)p_part, nullptr, nullptr,
            MROWS, XDBL_N, D_INNER, D_INNER, XDBL_N);
    }
    // 3b) reduce partials -> dt bf16 hi/lo + bc fp32
    finalize_xdbl<<<(MROWS * (XDBL_N / 4) + 255) / 256, 256>>>();

    // 4) delta = softplus(dt @ W_dt + b_dt) (bf16 3-term)
    {
        dim3 grid(D_INNER / 128, MROWS / 128, 1);
        mma_gemm<2,0><<<grid, 256, SM_M0>>>(
            p_dth, p_dtl, p_wdth, p_wdtl,
            (float*)p_delta, nullptr, b_dt,
            MROWS, D_INNER, DT_RANK, DT_RANK, D_INNER);
    }
    // 6) selective scan + gating -> u (fp16)
    scan_kernel<<<(BATCH * D_INNER) / 16, 256>>>(Dvec);

    // 7) out = u @ W_out (fp16 single)
    {
        dim3 grid(D_MODEL / 128, MROWS / 128, 1);
        mma_gemm<0,2><<<grid, 256, SM_M2>>>(
            p_uh, nullptr, p_wouth, nullptr,
            out, nullptr, nullptr,
            MROWS, D_MODEL, D_INNER, D_INNER, D_MODEL);
    }
}

// round 16
// speedup vs baseline: 1.0456x; 1.0456x over previous
#include <cuda_runtime.h>
#include <cuda_bf16.h>
#include <cuda_fp16.h>

// ---------------------------------------------------------------------------
// Problem constants
// ---------------------------------------------------------------------------
#define D_MODEL  1024
#define D_INNER  2048
#define D_STATE  16
#define D_CONV   4
#define DT_RANK  64
#define BATCH    2
#define SEQLEN   2048
#define MROWS    (BATCH * SEQLEN)         // 4096
#define XDBL_N   (DT_RANK + 2 * D_STATE)  // 96
#define KSLICES  8                        // split-K factor for GEMM2

// ---------------------------------------------------------------------------
// Scratch (static device globals; no allocation allowed)
// ---------------------------------------------------------------------------
__device__ float  g_xraw [MROWS * D_INNER];    // x pre-conv (fp32)
__device__ __half g_zs_h [MROWS * D_INNER];    // silu(z) fp16 (scan input)
__device__ float  g_bc   [MROWS * 32];         // B|C fp32 (scan)
__device__ float  g_delta[MROWS * D_INNER];    // softplus(dt) fp32
__device__ float  g_xdbl_part[KSLICES * MROWS * XDBL_N];  // split-K partials

// fp16 single activations (A of GEMM1/4)
__device__ __half g_hid_h[MROWS * D_MODEL];
__device__ __half g_u_h  [MROWS * D_INNER];
// bf16 hi/lo activations (A of GEMM2/3 + scan xc source)
__device__ __nv_bfloat16 g_xc_h [MROWS * D_INNER];
__device__ __nv_bfloat16 g_xc_l [MROWS * D_INNER];
__device__ __nv_bfloat16 g_dt_h [MROWS * DT_RANK];
__device__ __nv_bfloat16 g_dt_l [MROWS * DT_RANK];

__device__ float g_Aneg [D_INNER * D_STATE];   // -exp(A_log) * log2(e)

// transposed ([N][K]) weights: fp16 SINGLE for GEMM1/4, bf16 hi/lo for GEMM2/3
__device__ __half        g_WinT_h [4096 * 1024];
__device__ __half        g_WoutT_h[1024 * 2048];
__device__ __nv_bfloat16 g_WxT_h  [96 * 2048];
__device__ __nv_bfloat16 g_WxT_l  [96 * 2048];
__device__ __nv_bfloat16 g_WdtT_h [2048 * 64];
__device__ __nv_bfloat16 g_WdtT_l [2048 * 64];

__device__ __forceinline__ float sigmoidf_(float v) {
    return 1.0f / (1.0f + __expf(-v));
}
__device__ __forceinline__ unsigned smem_u32(const void* p) {
    unsigned a;
    asm("{ .reg .u64 t; cvta.to.shared.u64 t, %1; cvt.u32.u64 %0, t; }"
        : "=r"(a) : "l"(p));
    return a;
}
__device__ __forceinline__ unsigned pkbf(float a, float b) {
    __nv_bfloat162 p = __floats2bfloat162_rn(a, b);
    return *reinterpret_cast<unsigned*>(&p);
}
__device__ __forceinline__ unsigned pkhf(float a, float b) {
    __half2 p = __floats2half2_rn(a, b);
    return *reinterpret_cast<unsigned*>(&p);
}
__device__ __forceinline__ float residb(float v) {
    return v - __bfloat162float(__float2bfloat16(v));
}

#define LDSM4(r, addr)                                                        \
    asm volatile("ldmatrix.sync.aligned.m8n8.x4.shared.b16 {%0,%1,%2,%3}, [%4];" \
        : "=r"((r)[0]), "=r"((r)[1]), "=r"((r)[2]), "=r"((r)[3]) : "r"(addr))

#define MMABF16(c, a, b0, b1)                                                 \
    asm volatile("mma.sync.aligned.m16n8k16.row.col.f32.bf16.bf16.f32 "       \
        "{%0,%1,%2,%3}, {%4,%5,%6,%7}, {%8,%9}, {%0,%1,%2,%3};"               \
        : "+f"((c)[0]), "+f"((c)[1]), "+f"((c)[2]), "+f"((c)[3])              \
        : "r"((a)[0]), "r"((a)[1]), "r"((a)[2]), "r"((a)[3]), "r"(b0), "r"(b1))

#define MMAF16(c, a, b0, b1)                                                  \
    asm volatile("mma.sync.aligned.m16n8k16.row.col.f32.f16.f16.f32 "         \
        "{%0,%1,%2,%3}, {%4,%5,%6,%7}, {%8,%9}, {%0,%1,%2,%3};"               \
        : "+f"((c)[0]), "+f"((c)[1]), "+f"((c)[2]), "+f"((c)[3])              \
        : "r"((a)[0]), "r"((a)[1]), "r"((a)[2]), "r"((a)[3]), "r"(b0), "r"(b1))

__device__ __forceinline__ void cpa16(unsigned dst, const void* src, int sz) {
    asm volatile("cp.async.cg.shared.global [%0], [%1], 16, %2;"
                 :: "r"(dst), "l"(src), "r"(sz));
}
#define CPA_COMMIT() asm volatile("cp.async.commit_group;" ::: "memory")
#define CPA_WAIT0()  asm volatile("cp.async.wait_group 0;" ::: "memory")
#define CPA_WAIT1()  asm volatile("cp.async.wait_group 1;" ::: "memory")

// ---------------------------------------------------------------------------
// Weight prep
// ---------------------------------------------------------------------------
__global__ void prep_w_bf(const float* __restrict__ W,
                          __nv_bfloat16* __restrict__ hT,
                          __nv_bfloat16* __restrict__ lT, int K, int N)
{
    __shared__ float t[32][33];
    int k0 = blockIdx.x * 32, n0 = blockIdx.y * 32;
    int tx = threadIdx.x, ty = threadIdx.y;
#pragma unroll
    for (int i = 0; i < 4; i++) {
        int k = k0 + ty + i * 8;
        t[ty + i * 8][tx] = (k < K && n0 + tx < N) ? W[(size_t)k * N + n0 + tx] : 0.f;
    }
    __syncthreads();
#pragma unroll
    for (int i = 0; i < 4; i++) {
        int n = n0 + ty + i * 8, k = k0 + tx;
        if (n < N && k < K) {
            float v = t[tx][ty + i * 8];
            __nv_bfloat16 h = __float2bfloat16(v);
            hT[(size_t)n * K + k] = h;
            lT[(size_t)n * K + k] = __float2bfloat16(v - __bfloat162float(h));
        }
    }
}

// fp32 -> transposed single fp16 [N][K]
__global__ void prep_w_f16s(const float* __restrict__ W,
                            __half* __restrict__ hT, int K, int N)
{
    __shared__ float t[32][33];
    int k0 = blockIdx.x * 32, n0 = blockIdx.y * 32;
    int tx = threadIdx.x, ty = threadIdx.y;
#pragma unroll
    for (int i = 0; i < 4; i++) {
        int k = k0 + ty + i * 8;
        t[ty + i * 8][tx] = (k < K && n0 + tx < N) ? W[(size_t)k * N + n0 + tx] : 0.f;
    }
    __syncthreads();
#pragma unroll
    for (int i = 0; i < 4; i++) {
        int n = n0 + ty + i * 8, k = k0 + tx;
        if (n < N && k < K)
            hT[(size_t)n * K + k] = __float2half_rn(t[tx][ty + i * 8]);
    }
}

// hidden fp32 -> fp16 single
__global__ void conv_hidden(const float* __restrict__ H)
{
    size_t i = (size_t)(blockIdx.x * blockDim.x + threadIdx.x) * 8;
    if (i >= (size_t)MROWS * D_MODEL) return;
    float4 v0 = *(const float4*)(H + i);
    float4 v1 = *(const float4*)(H + i + 4);
    uint4 h = make_uint4(pkhf(v0.x, v0.y), pkhf(v0.z, v0.w),
                         pkhf(v1.x, v1.y), pkhf(v1.z, v1.w));
    *(uint4*)(g_hid_h + i) = h;
}

// ---------------------------------------------------------------------------
// warp-MMA GEMM, cp.async pipelined.
// MODE 0: bf16 3-term (A hi/lo + B hi/lo), 2-stage      (GEMM2/3)
// MODE 2: fp16 single A x single B, 1 MMA/k16, 3-stage  (GEMM1/4)
// EPI 0: plain  EPI 1: xz split (x fp32, silu(z) fp16)  EPI 2: bias+softplus
// EPI 4: split-K partial
// ---------------------------------------------------------------------------
#define APITCH 80         // bytes per smem row (40 halves)
#define TILEB  10240      // one 128-row tile

template <int EPI, int MODE>
__global__ __launch_bounds__(256, 2)
void mma_gemm(const void* __restrict__ Ah_, const void* __restrict__ Al_,
              const void* __restrict__ BTh_, const void* __restrict__ BTl_,
              float* __restrict__ C0, float* __restrict__ C1,
              const float* __restrict__ bias,
              int M, int N, int K, int lda, int ldc)
{
    constexpr int ATILES = (MODE == 0) ? 2 : 1;
    constexpr int BTILES = (MODE == 2) ? 1 : 2;
    constexpr int NSTAGE = (MODE == 0) ? 2 : 3;
    constexpr int SB = (ATILES + BTILES) * TILEB;   // stage bytes

    extern __shared__ __align__(16) char sm[];
    const unsigned short* Ah = (const unsigned short*)Ah_;
    const unsigned short* Al = (const unsigned short*)Al_;
    const unsigned short* BTh = (const unsigned short*)BTh_;
    const unsigned short* BTl = (const unsigned short*)BTl_;

    const int tid = threadIdx.x, lane = tid & 31, wid = tid >> 5;
    const int row0 = blockIdx.y * 128, col0 = blockIdx.x * 128;
    const int wm = (wid >> 2) * 64, wn = (wid & 3) * 32;

    const int lrow = tid >> 1;
    const int kb = (tid & 1) * 16;

    float acc[4][4][4];
#pragma unroll
    for (int i = 0; i < 4; i++)
#pragma unroll
        for (int j = 0; j < 4; j++)
#pragma unroll
            for (int q = 0; q < 4; q++) acc[i][j][q] = 0.f;

    const unsigned smb = smem_u32(sm);
    const unsigned aOff = (wm + (lane & 15)) * APITCH + (lane >> 4) * 16;
    const unsigned bOff = ATILES * TILEB + (wn + (lane & 15)) * APITCH + (lane >> 4) * 16;

    const int gnB = col0 + lrow;
    const int bsz = (gnB < N) ? 16 : 0;
    const int gnC = (gnB < N) ? gnB : (N - 1);
    const unsigned dA = lrow * APITCH + kb * 2;
    const unsigned dB = ATILES * TILEB + lrow * APITCH + kb * 2;

    const int ktn = (K >> 5) / gridDim.z;
    const int ktb = blockIdx.z * ktn;

    auto issue = [&](int kt, int st) {
        const int k0 = kt << 5;
        const unsigned sbase = smb + st * SB;
        const unsigned short* aph = Ah + (size_t)(row0 + lrow) * lda + k0 + kb;
        cpa16(sbase + dA, aph, 16);
        cpa16(sbase + dA + 16, aph + 8, 16);
        if (MODE == 0) {
            const unsigned short* apl = Al + (size_t)(row0 + lrow) * lda + k0 + kb;
            cpa16(sbase + dA + TILEB, apl, 16);
            cpa16(sbase + dA + TILEB + 16, apl + 8, 16);
        }
        const unsigned short* bph = BTh + (size_t)gnC * K + k0 + kb;
        cpa16(sbase + dB, bph, bsz);
        cpa16(sbase + dB + 16, bph + 8, bsz);
        if (MODE != 2) {
            const unsigned short* bpl = BTl + (size_t)gnC * K + k0 + kb;
            cpa16(sbase + dB + TILEB, bpl, bsz);
            cpa16(sbase + dB + TILEB + 16, bpl + 8, bsz);
        }
        CPA_COMMIT();
    };

    auto compute = [&](int st) {
        const unsigned sbase = smb + st * SB;
        const unsigned aHi = sbase + aOff;
        const unsigned bHi = sbase + bOff;
#pragma unroll
        for (int ks = 0; ks < 2; ks++) {
            const unsigned koff = ks * 32;
            unsigned ah[4][4], bh[2][4];
#pragma unroll
            for (int mt = 0; mt < 4; mt++)
                LDSM4(ah[mt], aHi + mt * (16 * APITCH) + koff);
#pragma unroll
            for (int g = 0; g < 2; g++)
                LDSM4(bh[g], bHi + g * (16 * APITCH) + koff);
            if (MODE == 0) {
                unsigned al[4][4], bl[2][4];
#pragma unroll
                for (int mt = 0; mt < 4; mt++)
                    LDSM4(al[mt], aHi + TILEB + mt * (16 * APITCH) + koff);
#pragma unroll
                for (int g = 0; g < 2; g++)
                    LDSM4(bl[g], bHi + TILEB + g * (16 * APITCH) + koff);
#pragma unroll
                for (int mt = 0; mt < 4; mt++)
#pragma unroll
                    for (int nt = 0; nt < 4; nt++) {
                        const int g = nt >> 1, o = nt & 1;
                        MMABF16(acc[mt][nt], ah[mt], bh[g][o], bh[g][2 + o]);
                        MMABF16(acc[mt][nt], ah[mt], bl[g][o], bl[g][2 + o]);
                        MMABF16(acc[mt][nt], al[mt], bh[g][o], bh[g][2 + o]);
                    }
            } else {
#pragma unroll
                for (int mt = 0; mt < 4; mt++)
#pragma unroll
                    for (int nt = 0; nt < 4; nt++) {
                        const int g = nt >> 1, o = nt & 1;
                        MMAF16(acc[mt][nt], ah[mt], bh[g][o], bh[g][2 + o]);
                    }
            }
        }
    };

    if (NSTAGE == 3) {
        // 3-stage, one barrier per iteration (stage (t+2)%3 was consumed at t-1)
        issue(ktb, 0);
        if (ktn > 1) issue(ktb + 1, 1);
        for (int t = 0; t < ktn; t++) {
            if (t + 1 < ktn) CPA_WAIT1(); else CPA_WAIT0();
            __syncthreads();
            if (t + 2 < ktn) issue(ktb + t + 2, (t + 2) % 3);
            compute(t % 3);
        }
    } else {
        issue(ktb, 0);
        for (int t = 0; t < ktn; t++) {
            const int cur = t & 1;
            if (t + 1 < ktn) issue(ktb + t + 1, cur ^ 1);
            if (t + 1 < ktn) CPA_WAIT1(); else CPA_WAIT0();
            __syncthreads();
            compute(cur);
            __syncthreads();
        }
    }

    // ---- epilogue ----
    const int g = lane >> 2, tg = (lane & 3) * 2;
#pragma unroll
    for (int mt = 0; mt < 4; mt++) {
#pragma unroll
        for (int nt = 0; nt < 4; nt++) {
            float* c = acc[mt][nt];
            int r0 = row0 + wm + mt * 16 + g;
            int r1 = r0 + 8;
            int cc = col0 + wn + nt * 8 + tg;
            if (EPI == 0) {
                if (cc < N) {
                    *(float2*)&C0[(size_t)r0 * ldc + cc] = make_float2(c[0], c[1]);
                    *(float2*)&C0[(size_t)r1 * ldc + cc] = make_float2(c[2], c[3]);
                }
            } else if (EPI == 1) {
                int h = cc >> 1;    // cc even: c0/c2 -> x col h, c1/c3 -> z col h
                __half* Z = (__half*)C1;
                C0[(size_t)r0 * D_INNER + h] = c[0];
                Z [(size_t)r0 * D_INNER + h] = __float2half_rn(c[1] * sigmoidf_(c[1]));
                C0[(size_t)r1 * D_INNER + h] = c[2];
                Z [(size_t)r1 * D_INNER + h] = __float2half_rn(c[3] * sigmoidf_(c[3]));
            } else if (EPI == 2) {
                float b0v = bias[cc], b1v = bias[cc + 1];
                float a0 = c[0] + b0v, a1 = c[1] + b1v;
                float a2 = c[2] + b0v, a3 = c[3] + b1v;
                a0 = (a0 > 20.f) ? a0 : log1pf(__expf(a0));
                a1 = (a1 > 20.f) ? a1 : log1pf(__expf(a1));
                a2 = (a2 > 20.f) ? a2 : log1pf(__expf(a2));
                a3 = (a3 > 20.f) ? a3 : log1pf(__expf(a3));
                *(float2*)&C0[(size_t)r0 * ldc + cc] = make_float2(a0, a1);
                *(float2*)&C0[(size_t)r1 * ldc + cc] = make_float2(a2, a3);
            } else { // EPI 4: split-K partial store
                if (cc < N) {
                    float* dst = C0 + (size_t)blockIdx.z * M * ldc;
                    *(float2*)&dst[(size_t)r0 * ldc + cc] = make_float2(c[0], c[1]);
                    *(float2*)&dst[(size_t)r1 * ldc + cc] = make_float2(c[2], c[3]);
                }
            }
        }
    }
}

// ---------------------------------------------------------------------------
// finalize split-K xdbl
// ---------------------------------------------------------------------------
__global__ void finalize_xdbl()
{
    int idx = blockIdx.x * blockDim.x + threadIdx.x;
    if (idx >= MROWS * (XDBL_N / 4)) return;
    int row = idx / 24;
    int c4 = (idx % 24) * 4;
    float4 s = make_float4(0.f, 0.f, 0.f, 0.f);
#pragma unroll
    for (int z = 0; z < KSLICES; z++) {
        float4 v = *(const float4*)&g_xdbl_part[(size_t)z * MROWS * XDBL_N
                                                + (size_t)row * XDBL_N + c4];
        s.x += v.x; s.y += v.y; s.z += v.z; s.w += v.w;
    }
    if (c4 < DT_RANK) {
        size_t o = (size_t)row * DT_RANK + c4;
        *(uint2*)&g_dt_h[o] = make_uint2(pkbf(s.x, s.y), pkbf(s.z, s.w));
        *(uint2*)&g_dt_l[o] = make_uint2(pkbf(residb(s.x), residb(s.y)),
                                         pkbf(residb(s.z), residb(s.w)));
    } else {
        *(float4*)&g_bc[(size_t)row * 32 + (c4 - DT_RANK)] = s;
    }
}

// ---------------------------------------------------------------------------
// Depthwise conv (SAME pad lo=1 hi=2) + bias + silu; writes bf16 hi/lo ONLY
// ---------------------------------------------------------------------------
__global__ void conv_silu_kernel(const float* __restrict__ ck,
                                 const float* __restrict__ cb)
{
    int idx = blockIdx.x * blockDim.x + threadIdx.x;
    if (idx >= MROWS * (D_INNER / 4)) return;
    int row = idx >> 9;
    int d = (idx & 511) << 2;
    int b = row >> 11;
    int l = row & (SEQLEN - 1);

    float4 acc = *(const float4*)&cb[d];
#pragma unroll
    for (int w = 0; w < D_CONV; w++) {
        int ls = l + w - 1;
        if (ls >= 0 && ls < SEQLEN) {
            float4 xv = *(const float4*)&g_xraw[((size_t)(b * SEQLEN + ls)) * D_INNER + d];
            float4 kv = *(const float4*)&ck[w * D_INNER + d];
            acc.x += xv.x * kv.x; acc.y += xv.y * kv.y;
            acc.z += xv.z * kv.z; acc.w += xv.w * kv.w;
        }
    }
    acc.x *= sigmoidf_(acc.x); acc.y *= sigmoidf_(acc.y);
    acc.z *= sigmoidf_(acc.z); acc.w *= sigmoidf_(acc.w);
    size_t o = (size_t)row * D_INNER + d;
    *(uint2*)&g_xc_h[o] = make_uint2(pkbf(acc.x, acc.y), pkbf(acc.z, acc.w));
    *(uint2*)&g_xc_l[o] = make_uint2(pkbf(residb(acc.x), residb(acc.y)),
                                     pkbf(residb(acc.z), residb(acc.w)));
}

// A = -exp(A_log) * log2(e)  (scan uses exp2f)
__global__ void aneg_kernel(const float* __restrict__ A_log)
{
    int i = blockIdx.x * blockDim.x + threadIdx.x;
    if (i < D_INNER * D_STATE) g_Aneg[i] = -__expf(A_log[i]) * 1.4426950408889634f;
}

// ---------------------------------------------------------------------------
// Selective scan fused with gating; WIDE vectorized staging (this round's fix:
// R15 used per-element 2-byte loads here — LSU-issue bound, regressed).
// Each thread stages one row-quarter: 3x float4 + 3x uint2 wide loads.
// ---------------------------------------------------------------------------
#define TCHUNK 64

__global__ __launch_bounds__(256)
void scan_kernel(const float* __restrict__ Dvec)
{
    __shared__ float sB [TCHUNK][D_STATE];
    __shared__ float sC [TCHUNK][D_STATE];
    __shared__ float sDl[TCHUNK][16];
    __shared__ float sX [TCHUNK][16];
    __shared__ float sZ [TCHUNK][16];

    const int tid = threadIdx.x;
    const int b = blockIdx.x >> 7;
    const int d0 = (blockIdx.x & 127) * 16;
    const int warp = tid >> 5;
    const int half = (tid >> 4) & 1;
    const int n = tid & 15;
    const int dl = warp * 2 + half;
    const int d = d0 + dl;

    const float An = g_Aneg[d * D_STATE + n];   // includes log2(e)
    const float Dd = Dvec[d];
    float st = 0.0f;
    const long base_row = (long)b * SEQLEN;

    const int srow = tid >> 2;        // 0..63 : staged row
    const int q    = (tid & 3) * 4;   // 0,4,8,12 : quarter offset

    for (int c = 0; c < SEQLEN / TCHUNK; c++) {
        const int t0 = c * TCHUNK;
        __syncthreads();
        {
            const long row = base_row + t0 + srow;
            // B | C (fp32, [row][32])
            float4 vb = *(const float4*)&g_bc[row * 32 + q];
            float4 vc = *(const float4*)&g_bc[row * 32 + 16 + q];
            *(float4*)&sB[srow][q] = vb;
            *(float4*)&sC[srow][q] = vc;
            // delta (fp32)
            float4 vd = *(const float4*)&g_delta[row * D_INNER + d0 + q];
            *(float4*)&sDl[srow][q] = vd;
            // xc = hi + lo (bf16 pairs, 4 elements = uint2)
            uint2 xh = *(const uint2*)&g_xc_h[row * D_INNER + d0 + q];
            uint2 xl = *(const uint2*)&g_xc_l[row * D_INNER + d0 + q];
            __nv_bfloat162 h0 = *reinterpret_cast<__nv_bfloat162*>(&xh.x);
            __nv_bfloat162 h1 = *reinterpret_cast<__nv_bfloat162*>(&xh.y);
            __nv_bfloat162 l0 = *reinterpret_cast<__nv_bfloat162*>(&xl.x);
            __nv_bfloat162 l1 = *reinterpret_cast<__nv_bfloat162*>(&xl.y);
            float4 vx;
            vx.x = __bfloat162float(h0.x) + __bfloat162float(l0.x);
            vx.y = __bfloat162float(h0.y) + __bfloat162float(l0.y);
            vx.z = __bfloat162float(h1.x) + __bfloat162float(l1.x);
            vx.w = __bfloat162float(h1.y) + __bfloat162float(l1.y);
            *(float4*)&sX[srow][q] = vx;
            // zs (fp16, 4 elements = uint2)
            uint2 zz = *(const uint2*)&g_zs_h[row * D_INNER + d0 + q];
            __half2 z0 = *reinterpret_cast<__half2*>(&zz.x);
            __half2 z1 = *reinterpret_cast<__half2*>(&zz.y);
            float4 vz;
            vz.x = __half2float(z0.x); vz.y = __half2float(z0.y);
            vz.z = __half2float(z1.x); vz.w = __half2float(z1.y);
            *(float4*)&sZ[srow][q] = vz;
        }
        __syncthreads();

#pragma unroll 4
        for (int tt = 0; tt < TCHUNK; tt++) {
            float dv = sDl[tt][dl];
            float xv = sX[tt][dl];
            float bv = sB[tt][n];
            float cv = sC[tt][n];
            float dA = exp2f(dv * An);
            st = __fmaf_rn(dA, st, dv * xv * bv);
            float p = st * cv;
            p += __shfl_xor_sync(0xffffffffu, p, 1, 16);
            p += __shfl_xor_sync(0xffffffffu, p, 2, 16);
            p += __shfl_xor_sync(0xffffffffu, p, 4, 16);
            p += __shfl_xor_sync(0xffffffffu, p, 8, 16);
            if (n == 0) {
                long row = base_row + t0 + tt;
                float uv = (p + xv * Dd) * sZ[tt][dl];
                g_u_h[row * D_INNER + d] = __float2half_rn(uv);
            }
        }
    }
}

// ---------------------------------------------------------------------------
// Host launcher
// ---------------------------------------------------------------------------
extern "C" void kernel_launch(void* const* d_in, const int* in_sizes, int n_in,
                              void* d_out, int out_size)
{
    const float* hidden = (const float*)d_in[0];
    const float* W_in   = (const float*)d_in[1];
    const float* ck     = (const float*)d_in[2];
    const float* cb     = (const float*)d_in[3];
    const float* W_x    = (const float*)d_in[4];
    const float* W_dt   = (const float*)d_in[5];
    const float* b_dt   = (const float*)d_in[6];
    const float* A_log  = (const float*)d_in[7];
    const float* Dvec   = (const float*)d_in[8];
    const float* W_out  = (const float*)d_in[9];
    float* out = (float*)d_out;

    void *p_xraw, *p_zsh, *p_delta, *p_part;
    cudaGetSymbolAddress(&p_xraw,  g_xraw);
    cudaGetSymbolAddress(&p_zsh,   g_zs_h);
    cudaGetSymbolAddress(&p_delta, g_delta);
    cudaGetSymbolAddress(&p_part,  g_xdbl_part);

    void *p_hidh, *p_xch, *p_xcl, *p_dth, *p_dtl, *p_uh;
    cudaGetSymbolAddress(&p_hidh, g_hid_h);
    cudaGetSymbolAddress(&p_xch,  g_xc_h);   cudaGetSymbolAddress(&p_xcl,  g_xc_l);
    cudaGetSymbolAddress(&p_dth,  g_dt_h);   cudaGetSymbolAddress(&p_dtl,  g_dt_l);
    cudaGetSymbolAddress(&p_uh,   g_u_h);

    void *p_winh, *p_wxh, *p_wxl, *p_wdth, *p_wdtl, *p_wouth;
    cudaGetSymbolAddress(&p_winh,  g_WinT_h);
    cudaGetSymbolAddress(&p_wxh,   g_WxT_h);   cudaGetSymbolAddress(&p_wxl,   g_WxT_l);
    cudaGetSymbolAddress(&p_wdth,  g_WdtT_h);  cudaGetSymbolAddress(&p_wdtl,  g_WdtT_l);
    cudaGetSymbolAddress(&p_wouth, g_WoutT_h);

    const int SM_M0 = 2 * 4 * TILEB;   // MODE0 2-stage: 81920
    const int SM_M2 = 3 * 2 * TILEB;   // MODE2 3-stage: 61440
    cudaFuncSetAttribute(mma_gemm<1,2>, cudaFuncAttributeMaxDynamicSharedMemorySize, SM_M2);
    cudaFuncSetAttribute(mma_gemm<0,2>, cudaFuncAttributeMaxDynamicSharedMemorySize, SM_M2);
    cudaFuncSetAttribute(mma_gemm<4,0>, cudaFuncAttributeMaxDynamicSharedMemorySize, SM_M0);
    cudaFuncSetAttribute(mma_gemm<2,0>, cudaFuncAttributeMaxDynamicSharedMemorySize, SM_M0);

    dim3 tb(32, 8);
    // 0) input conversion + weight prep
    conv_hidden<<<(MROWS * D_MODEL / 8 + 255) / 256, 256>>>(hidden);
    prep_w_f16s<<<dim3(D_MODEL / 32, (2 * D_INNER) / 32), tb>>>(W_in,
        (__half*)p_winh, D_MODEL, 2 * D_INNER);
    prep_w_bf<<<dim3(D_INNER / 32, 3), tb>>>(W_x,
        (__nv_bfloat16*)p_wxh, (__nv_bfloat16*)p_wxl, D_INNER, XDBL_N);
    prep_w_bf<<<dim3(DT_RANK / 32, D_INNER / 32), tb>>>(W_dt,
        (__nv_bfloat16*)p_wdth, (__nv_bfloat16*)p_wdtl, DT_RANK, D_INNER);
    prep_w_f16s<<<dim3(D_INNER / 32, D_MODEL / 32), tb>>>(W_out,
        (__half*)p_wouth, D_INNER, D_MODEL);

    // 1) xz = hidden @ W_in (fp16 single) ; split into x_raw fp32 / silu(z) fp16
    {
        dim3 grid((2 * D_INNER) / 128, MROWS / 128, 1);
        mma_gemm<1,2><<<grid, 256, SM_M2>>>(
            p_hidh, nullptr, p_winh, nullptr,
            (float*)p_xraw, (float*)p_zsh, nullptr,
            MROWS, 2 * D_INNER, D_MODEL, D_MODEL, 2 * D_INNER);
    }
    aneg_kernel<<<(D_INNER * D_STATE + 255) / 256, 256>>>(A_log);
    // 2) depthwise conv + bias + silu (bf16 hi/lo only)
    {
        int threads = MROWS * (D_INNER / 4);
        conv_silu_kernel<<<(threads + 255) / 256, 256>>>(ck, cb);
    }
    // 3) x_dbl = xc @ W_x (bf16 3-term, split-K x8 -> partials)
    {
        dim3 grid(1, MROWS / 128, KSLICES);
        mma_gemm<4,0><<<grid, 256, SM_M0>>>(
            p_xch, p_xcl, p_wxh, p_wxl,
            (float*)p_part, nullptr, nullptr,
            MROWS, XDBL_N, D_INNER, D_INNER, XDBL_N);
    }
    // 3b) reduce partials -> dt bf16 hi/lo + bc fp32
    finalize_xdbl<<<(MROWS * (XDBL_N / 4) + 255) / 256, 256>>>();

    // 4) delta = softplus(dt @ W_dt + b_dt) (bf16 3-term)
    {
        dim3 grid(D_INNER / 128, MROWS / 128, 1);
        mma_gemm<2,0><<<grid, 256, SM_M0>>>(
            p_dth, p_dtl, p_wdth, p_wdtl,
            (float*)p_delta, nullptr, b_dt,
            MROWS, D_INNER, DT_RANK, DT_RANK, D_INNER);
    }
    // 6) selective scan + gating -> u (fp16)
    scan_kernel<<<(BATCH * D_INNER) / 16, 256>>>(Dvec);

    // 7) out = u @ W_out (fp16 single)
    {
        dim3 grid(D_MODEL / 128, MROWS / 128, 1);
        mma_gemm<0,2><<<grid, 256, SM_M2>>>(
            p_uh, nullptr, p_wouth, nullptr,
            out, nullptr, nullptr,
            MROWS, D_MODEL, D_INNER, D_INNER, D_MODEL);
    }
}